// round 3
// baseline (speedup 1.0000x reference)
#include <cuda_runtime.h>
#include <cuda_bf16.h>

typedef unsigned long long u64;
__device__ __forceinline__ u64 pk2(float lo, float hi) {
    u64 r; asm("mov.b64 %0, {%1, %2};" : "=l"(r) : "f"(lo), "f"(hi)); return r;
}
__device__ __forceinline__ void unpk2(u64 v, float& lo, float& hi) {
    asm("mov.b64 {%0, %1}, %2;" : "=f"(lo), "=f"(hi) : "l"(v));
}
__device__ __forceinline__ u64 mul2(u64 a, u64 b) {
    u64 r; asm("mul.rn.f32x2 %0, %1, %2;" : "=l"(r) : "l"(a), "l"(b)); return r;
}
__device__ __forceinline__ u64 fma2(u64 a, u64 b, u64 c) {
    u64 r; asm("fma.rn.f32x2 %0, %1, %2, %3;" : "=l"(r) : "l"(a), "l"(b), "l"(c)); return r;
}

#define PAIRS 4   // 8 samples per thread

// Single fused kernel. Each block redundantly computes the 100 bilinear-form
// coefficients (cheap, parallel: shuffle-based 16x16 unitary sim, ~1us), then
// processes its slice of the batch with packed f32x2 math.
__global__ void __launch_bounds__(256)
qnn_fused(const float4* __restrict__ x, float* __restrict__ out,
          const float* __restrict__ w, int npair)
{
    __shared__ float  wsh[36];
    __shared__ float2 S[16][16];     // S[col][k] = U[k][col]
    __shared__ float  coefS[100];
    __shared__ u64    scp[100];
    const int tid = threadIdx.x;

    if (tid < 36) wsh[tid] = w[tid];
    if (tid >= 64 && tid < 164) coefS[tid - 64] = 0.f;
    __syncthreads();

    // ---------- per-block setup: simulate the 16x16 variational unitary ----------
    {
        const int col = tid >> 4, k = tid & 15;  // lane group of 16 = one column
        float ar = (k == col) ? 1.f : 0.f, ai = 0.f;

        // all 36 half-angle sincos up front (pipelined MUFU)
        float cc[36], ss[36];
        #pragma unroll
        for (int g = 0; g < 36; g++) __sincosf(0.5f * wsh[g], &ss[g], &cc[g]);

        // CNOT-ring inverse permutation: src amp index for this lane.
        // P = C(3->0) o C(2->3) o C(1->2) o C(0->1); Pinv applied to k:
        int sidx = k;
        if (sidx & 1) sidx ^= 8;   // inv C(3->0): if b0 flip b3
        if (sidx & 2) sidx ^= 1;   // inv C(2->3): if b1 flip b0
        if (sidx & 4) sidx ^= 2;   // inv C(1->2): if b2 flip b1
        if (sidx & 8) sidx ^= 4;   // inv C(0->1): if b3 flip b2

        #pragma unroll
        for (int l = 0; l < 3; l++) {
            #pragma unroll
            for (int q = 0; q < 4; q++) {
                const int pos = 3 - q, mask = 1 << pos;
                const int bit = (k >> pos) & 1;
                #pragma unroll
                for (int g = 0; g < 3; g++) {
                    const int gi = (l * 4 + q) * 3 + g;
                    const float c = cc[gi], s = ss[gi];
                    float nr, ni;
                    if (g == 2) {           // RZ (diagonal, no partner)
                        float t = bit ? -s : s;
                        nr = c * ar + t * ai;
                        ni = c * ai - t * ar;
                    } else {
                        float pr = __shfl_xor_sync(0xffffffffu, ar, mask);
                        float pi = __shfl_xor_sync(0xffffffffu, ai, mask);
                        if (g == 0) {       // RX: new = c*a + s*(i-coupled partner)
                            nr = c * ar + s * pi;
                            ni = c * ai - s * pr;
                        } else {            // RY
                            float t = bit ? s : -s;
                            nr = c * ar + t * pr;
                            ni = c * ai + t * pi;
                        }
                    }
                    ar = nr; ai = ni;
                }
            }
            // CNOT ring: one index shuffle per layer (width 16 = column group)
            ar = __shfl_sync(0xffffffffu, ar, sidx, 16);
            ai = __shfl_sync(0xffffffffu, ai, sidx, 16);
        }
        S[col][k] = make_float2(ar, ai);
    }
    __syncthreads();

    // ---------- A_q + collapse to 100 coefficients (atomic) ----------
    {
        const int i = tid >> 4, j = tid & 15;
        float s0 = 0.f, s1 = 0.f, s2 = 0.f, s3 = 0.f;
        #pragma unroll
        for (int k = 0; k < 16; k++) {
            float2 u = S[i][k], v = S[j][k];
            float p = u.x * v.x + u.y * v.y;
            s0 += ((k >> 3) & 1) ? -p : p;
            s1 += ((k >> 2) & 1) ? -p : p;
            s2 += ((k >> 1) & 1) ? -p : p;
            s3 += ( k       & 1) ? -p : p;
        }
        const int a_i = ((i >> 3) & 1) + ((i >> 1) & 1);
        const int b_i = ((i >> 2) & 1) + (i & 1);
        const int a_j = ((j >> 3) & 1) + ((j >> 1) & 1);
        const int b_j = ((j >> 2) & 1) + (j & 1);
        const int base = (a_i + a_j) * 5 + (b_i + b_j);
        atomicAdd(&coefS[base],      s0);
        atomicAdd(&coefS[25 + base], s1);
        atomicAdd(&coefS[50 + base], s2);
        atomicAdd(&coefS[75 + base], s3);
    }
    __syncthreads();
    if (tid < 100) { float v = coefS[tid]; scp[tid] = pk2(v, v); }
    __syncthreads();

    // ---------- batch phase: PAIRS pairs (2*PAIRS samples) per thread ----------
    const int t0      = blockIdx.x * 256 + tid;
    const int tstride = gridDim.x * 256;

    u64 f0[PAIRS][5], f1[PAIRS][5];
    #pragma unroll
    for (int p = 0; p < PAIRS; p++) {
        const int pi_ = t0 + p * tstride;
        float4 xv = (pi_ < npair) ? x[pi_] : make_float4(0.f, 0.f, 0.f, 0.f);
        float c0a, s0a, c1a, s1a, c0b, s0b, c1b, s1b;
        __sincosf(0.5f * xv.x, &s0a, &c0a);
        __sincosf(0.5f * xv.y, &s1a, &c1a);
        __sincosf(0.5f * xv.z, &s0b, &c0b);
        __sincosf(0.5f * xv.w, &s1b, &c1b);
        const u64 c0 = pk2(c0a, c0b), s0 = pk2(s0a, s0b);
        const u64 c1 = pk2(c1a, c1b), s1 = pk2(s1a, s1b);
        const u64 c02 = mul2(c0, c0), s02 = mul2(s0, s0), cs0 = mul2(c0, s0);
        const u64 c12 = mul2(c1, c1), s12 = mul2(s1, s1), cs1 = mul2(c1, s1);
        f0[p][0] = mul2(c02, c02); f0[p][1] = mul2(c02, cs0); f0[p][2] = mul2(cs0, cs0);
        f0[p][3] = mul2(cs0, s02); f0[p][4] = mul2(s02, s02);
        f1[p][0] = mul2(c12, c12); f1[p][1] = mul2(c12, cs1); f1[p][2] = mul2(cs1, cs1);
        f1[p][3] = mul2(cs1, s12); f1[p][4] = mul2(s12, s12);
    }

    // process q in groups of 2 so only 2 accumulators/pair are live -> fewer regs
    float2* out2 = (float2*)out;
    #pragma unroll
    for (int qg = 0; qg < 2; qg++) {
        u64 acc[2][PAIRS];
        #pragma unroll
        for (int qq = 0; qq < 2; qq++) {
            const int q = qg * 2 + qq;
            #pragma unroll
            for (int p = 0; p < PAIRS; p++) acc[qq][p] = 0ull;
            #pragma unroll
            for (int a = 0; a < 5; a++) {
                const u64 r0 = scp[q * 25 + a * 5 + 0];
                const u64 r1 = scp[q * 25 + a * 5 + 1];
                const u64 r2 = scp[q * 25 + a * 5 + 2];
                const u64 r3 = scp[q * 25 + a * 5 + 3];
                const u64 r4 = scp[q * 25 + a * 5 + 4];
                #pragma unroll
                for (int p = 0; p < PAIRS; p++) {
                    u64 ts = mul2(r4, f1[p][4]);
                    ts = fma2(r3, f1[p][3], ts);
                    ts = fma2(r2, f1[p][2], ts);
                    ts = fma2(r1, f1[p][1], ts);
                    ts = fma2(r0, f1[p][0], ts);
                    acc[qq][p] = fma2(ts, f0[p][a], acc[qq][p]);
                }
            }
        }
        #pragma unroll
        for (int p = 0; p < PAIRS; p++) {
            const int pi_ = t0 + p * tstride;
            if (pi_ < npair) {
                float qa0, qb0, qa1, qb1;
                unpk2(acc[0][p], qa0, qb0);   // q = 2*qg   (sampleA, sampleB)
                unpk2(acc[1][p], qa1, qb1);   // q = 2*qg+1
                // sampleA = 2*pi_, sampleB = 2*pi_+1; float2 index = sample*2 + qg
                out2[(long)4 * pi_ + qg]     = make_float2(qa0, qa1);
                out2[(long)4 * pi_ + 2 + qg] = make_float2(qb0, qb1);
            }
        }
    }
}

extern "C" void kernel_launch(void* const* d_in, const int* in_sizes, int n_in,
                              void* d_out, int out_size) {
    const float* x = (const float*)d_in[0];   // (B, 2)
    const float* w = (const float*)d_in[1];   // (3, 4, 3)
    const int n     = in_sizes[0] / 2;        // batch size (even)
    const int npair = n / 2;

    const int threads = (npair + PAIRS - 1) / PAIRS;
    const int blocks  = (threads + 255) / 256;
    qnn_fused<<<blocks, 256>>>((const float4*)x, (float*)d_out, w, npair);
}